// round 14
// baseline (speedup 1.0000x reference)
#include <cuda_runtime.h>
#include <math.h>

// Problem constants
#define MM       2048           // patches
#define NC       4              // compartments
#define NSTEPS   128
#define BETA_F   0.25f
#define TRAJ_ELEMS (NSTEPS * MM * (NC + 1))   // 1310720

// Launch geometry: 128 persistent blocks, 16 rows of R each, 256 threads
// (8 warps x 2 rows/warp). 1 block/SM via smem footprint => co-residency
// guaranteed on 148/152-SM GB300, so the software grid barrier cannot deadlock.
#define NBLK     128
#define ROWS     16
#define NTHREADS 256

// SMEM: R tile + x vector + ntot[16] + ppack[16] + xpack[16] + traj[80] + 16 dbl
#define SMEM_BYTES ((ROWS * MM + MM + 16 + 16 + 16 + 80) * 4 + 16 * 8)

// -------- persistent device state (monotonic; re-derived every launch) ------
__device__ float        g_x[MM];            // rho[:,0] (phase-A input vector)
__device__ float        g_p[MM];            // infect_prob (phase-B input vector)
__device__ float        g_part[NBLK * MM];  // per-block column partials (ntot)
__device__ double       g_bsum[NBLK];       // per-block |traj| sums (agreement)
__device__ unsigned int g_bar_in  = 0;      // monotonic arrival counter
__device__ unsigned int g_bar_gen = 0;      // monotonic generation counter

// R13 barrier unchanged (flat relaxed-atomic arrival, sleepless GPU-scope
// relaxed poll of single release word, acquire-side threadfence). The R14
// change is OUTSIDE the barrier: the pre-fence STG set is cut from ~96
// scalar stores to 4 STG.128 (traj stores deferred past the barrier, g_p/g_x
// packed), shrinking the fence drain term 36+k*n_STS from ~3.5K to ~180 cyc.
__device__ __forceinline__ void gridsync(unsigned int &gen) {
    __syncthreads();
    if (threadIdx.x == 0) {
        __threadfence();                                   // publish writes (release)
        unsigned int a = atomicAdd(&g_bar_in, 1u);
        if (a == gen * (unsigned)NBLK + (unsigned)(NBLK - 1)) {
            atomicAdd(&g_bar_gen, 1u);                     // last arriver releases
        } else {
            unsigned int f;
            do {   // dependent relaxed load: one L2 round trip per iteration
                asm volatile("ld.relaxed.gpu.u32 %0, [%1];"
                             : "=r"(f) : "l"(&g_bar_gen) : "memory");
            } while ((int)(f - (gen + 1u)) < 0);
            __threadfence();                               // acquire side
        }
        gen++;
    }
    __syncthreads();
}

__global__ void __launch_bounds__(NTHREADS, 1)
metasim_kernel(const float* __restrict__ Rg,
               const float* __restrict__ Tg,
               const float* __restrict__ rho0,
               float* __restrict__ out,
               int out_size)
{
    extern __shared__ float smem[];
    float*  Rs     = smem;                    // [ROWS][MM]
    float*  xs     = Rs + ROWS * MM;          // [MM]
    float*  ntot_s = xs + MM;                 // [16]
    float*  ppack  = ntot_s + 16;             // [16]  p staging for packed STG
    float*  xpack  = ppack + 16;              // [16]  x staging for packed STG
    float*  tbuf   = xpack + 16;              // [80]  traj staging (16 rows x 5)
    double* dsum   = (double*)(tbuf + 80);    // [16], 8B-aligned

    const int tid     = threadIdx.x;
    const int blk     = blockIdx.x;
    const int w       = tid >> 5;
    const int lane    = tid & 31;
    const int rowbase = blk * ROWS;

    unsigned int gen = 0;
    if (tid == 0) gen = *((volatile unsigned int*)&g_bar_gen);  // stable pre-barrier

    // ---- load this block's 16 rows of R into SMEM (once) ----
    {
        const float4* Rg4 = (const float4*)Rg + (size_t)rowbase * (MM / 4);
        float4* Rs4 = (float4*)Rs;
        #pragma unroll 4
        for (int k = tid; k < ROWS * MM / 4; k += NTHREADS) Rs4[k] = Rg4[k];
    }

    // ---- T (4x4) into registers ----
    float Tr[16];
    #pragma unroll
    for (int i = 0; i < 16; i++) Tr[i] = Tg[i];

    // ---- per-lane rho state: lane 0 -> row 2w, lane 1 -> row 2w+1 ----
    const int lrow  = 2 * w + ((lane < 2) ? lane : 0);  // local row idx (lane<2)
    const int myrow = rowbase + lrow;
    float r0 = 0.f, r1 = 0.f, r2 = 0.f, r3 = 0.f, kk = 0.f;
    if (lane < 2) {
        r0 = rho0[myrow * 4 + 0];
        r1 = rho0[myrow * 4 + 1];
        r2 = rho0[myrow * 4 + 2];
        r3 = rho0[myrow * 4 + 3];
        xpack[lrow] = r0;                       // initial x = rho0[:,0]
    }
    __syncthreads();                            // Rs + xpack ready
    if (tid < 4)                                // packed initial g_x store
        __stcg((float4*)&g_x[rowbase + 4 * tid], ((const float4*)xpack)[tid]);

    // ---- deterministic ntot: per-block column partials (no float atomics) ----
    for (int c = tid; c < MM; c += NTHREADS) {
        float s = 0.f;
        #pragma unroll
        for (int r = 0; r < ROWS; r++) s += Rs[r * MM + c];
        __stcg(&g_part[blk * MM + c], s);
    }

    gridsync(gen);                              // partials + g_x visible

    // ntot for own 16 columns (== own row indices), fixed summation order
    if (tid < ROWS) {
        const int c = rowbase + tid;
        float s = 0.f;
        for (int bb = 0; bb < NBLK; bb++) s += __ldcg(&g_part[bb * MM + c]);
        ntot_s[tid] = s;
    }
    __syncthreads();
    if (lane < 2) kk = -BETA_F / ntot_s[lrow];

    const float4* Rw0 = (const float4*)(Rs + (2 * w) * MM);
    const float4* Rw1 = (const float4*)(Rs + (2 * w + 1) * MM);
    float4* xs4 = (float4*)xs;

    double dAcc = 0.0;

    for (int t = 0; t < NSTEPS; t++) {
        // ================= Phase A: frac = R @ x, p = 1 - exp(-beta*frac/ntot)
        {
            const float4* gx4 = (const float4*)g_x;
            #pragma unroll
            for (int k = tid; k < MM / 4; k += NTHREADS) xs4[k] = __ldcg(gx4 + k);
        }
        __syncthreads();

        float a0 = 0.f, a1 = 0.f;
        #pragma unroll
        for (int j = 0; j < 16; j++) {
            const int c = j * 32 + lane;
            const float4 xv = xs4[c];
            const float4 u = Rw0[c];
            const float4 v = Rw1[c];
            a0 += u.x * xv.x + u.y * xv.y + u.z * xv.z + u.w * xv.w;
            a1 += v.x * xv.x + v.y * xv.y + v.z * xv.z + v.w * xv.w;
        }
        #pragma unroll
        for (int o = 16; o; o >>= 1) {
            a0 += __shfl_xor_sync(0xffffffffu, a0, o);
            a1 += __shfl_xor_sync(0xffffffffu, a1, o);
        }
        if (lane < 2) {
            const float fr = (lane == 0) ? a0 : a1;
            ppack[lrow] = 1.0f - expf(kk * fr);
        }
        __syncthreads();
        if (tid < 4)                            // packed g_p store: 4x STG.128
            __stcg((float4*)&g_p[rowbase + 4 * tid], ((const float4*)ppack)[tid]);
        gridsync(gen);

        // ================= Phase B: nw = R @ p, compartment update
        {
            const float4* gp4 = (const float4*)g_p;
            #pragma unroll
            for (int k = tid; k < MM / 4; k += NTHREADS) xs4[k] = __ldcg(gp4 + k);
        }
        __syncthreads();

        float b0 = 0.f, b1 = 0.f;
        #pragma unroll
        for (int j = 0; j < 16; j++) {
            const int c = j * 32 + lane;
            const float4 xv = xs4[c];
            const float4 u = Rw0[c];
            const float4 v = Rw1[c];
            b0 += u.x * xv.x + u.y * xv.y + u.z * xv.z + u.w * xv.w;
            b1 += v.x * xv.x + v.y * xv.y + v.z * xv.z + v.w * xv.w;
        }
        #pragma unroll
        for (int o = 16; o; o >>= 1) {
            b0 += __shfl_xor_sync(0xffffffffu, b0, o);
            b1 += __shfl_xor_sync(0xffffffffu, b1, o);
        }
        if (lane < 2) {
            const float acc = (lane == 0) ? b0 : b1;
            const float s   = r0 + r1 + r2 + r3;
            const float nw  = (1.0f - s) * acc;
            float n0 = r0 * Tr[0] + r1 * Tr[4] + r2 * Tr[8]  + r3 * Tr[12] + nw;
            float n1 = r0 * Tr[1] + r1 * Tr[5] + r2 * Tr[9]  + r3 * Tr[13];
            float n2 = r0 * Tr[2] + r1 * Tr[6] + r2 * Tr[10] + r3 * Tr[14];
            float n3 = r0 * Tr[3] + r1 * Tr[7] + r2 * Tr[11] + r3 * Tr[15];
            n0 = fminf(fmaxf(n0, 0.0f), 1e10f);
            n1 = fminf(fmaxf(n1, 0.0f), 1e10f);
            n2 = fminf(fmaxf(n2, 0.0f), 1e10f);
            n3 = fminf(fmaxf(n3, 0.0f), 1e10f);
            r0 = n0; r1 = n1; r2 = n2; r3 = n3;
            xpack[lrow] = n0;                             // next step's x (staged)

            const float S = 1.0f - (n0 + n1 + n2 + n3);   // AddSusceptibleLayer
            float* tb = tbuf + lrow * 5;                  // traj staged in SMEM
            tb[0] = S; tb[1] = n0; tb[2] = n1; tb[3] = n2; tb[4] = n3;
            dAcc += (double)(fabsf(S) + fabsf(n0) + fabsf(n1) + fabsf(n2) + fabsf(n3));
        }
        __syncthreads();
        if (tid < 4)                            // packed g_x store: 4x STG.128
            __stcg((float4*)&g_x[rowbase + 4 * tid], ((const float4*)xpack)[tid]);
        gridsync(gen);

        // Deferred traj flush AFTER the barrier: 20 STG.128, not in the fence
        // drain set of this barrier; retire to L2 long before the next fence.
        // tbuf is not rewritten until after the NEXT two barriers, so no race.
        if (tid < 20) {
            float4* dst = (float4*)(out + ((size_t)t * MM + rowbase) * (NC + 1));
            dst[tid] = ((const float4*)tbuf)[tid];
        }
    }

    // ---- agreement = mean(|traj|), fully deterministic reduction ----
    if (lane < 2) dsum[lrow] = dAcc;
    __syncthreads();
    if (tid == 0) {
        double s = 0.0;
        for (int i = 0; i < 16; i++) s += dsum[i];
        __stcg(&g_bsum[blk], s);
    }
    gridsync(gen);
    if (blk == 0 && tid == 0 && out_size > TRAJ_ELEMS) {
        double s = 0.0;
        for (int i = 0; i < NBLK; i++) s += __ldcg(&g_bsum[i]);
        out[TRAJ_ELEMS] = (float)(s / (double)TRAJ_ELEMS);
    }
}

extern "C" void kernel_launch(void* const* d_in, const int* in_sizes, int n_in,
                              void* d_out, int out_size)
{
    // Identify inputs by element count: R: 2048*2048, T: 4*4, rho0: 2048*4
    const float* R    = nullptr;
    const float* Tm   = nullptr;
    const float* rho0 = nullptr;
    for (int i = 0; i < n_in; i++) {
        if      (in_sizes[i] == MM * MM) R    = (const float*)d_in[i];
        else if (in_sizes[i] == NC * NC) Tm   = (const float*)d_in[i];
        else if (in_sizes[i] == MM * NC) rho0 = (const float*)d_in[i];
    }
    if (!R    && n_in > 0) R    = (const float*)d_in[0];
    if (!Tm   && n_in > 1) Tm   = (const float*)d_in[1];
    if (!rho0 && n_in > 2) rho0 = (const float*)d_in[2];

    cudaFuncSetAttribute(metasim_kernel,
                         cudaFuncAttributeMaxDynamicSharedMemorySize,
                         SMEM_BYTES);

    metasim_kernel<<<NBLK, NTHREADS, SMEM_BYTES>>>(R, Tm, rho0,
                                                   (float*)d_out, out_size);
}

// round 15
// speedup vs baseline: 1.0811x; 1.0811x over previous
#include <cuda_runtime.h>
#include <math.h>

// Problem constants
#define MM       2048           // patches
#define NC       4              // compartments
#define NSTEPS   128
#define BETA_F   0.25f
#define TRAJ_ELEMS (NSTEPS * MM * (NC + 1))   // 1310720

// Launch geometry: 128 persistent blocks, 16 rows of R each, 256 threads
// (8 warps x 2 rows/warp). 1 block/SM via smem footprint => co-residency
// guaranteed on 148/152-SM GB300, so the software grid barrier cannot deadlock.
#define NBLK     128
#define ROWS     16
#define NTHREADS 256

// SMEM: R tile (16*2048 f32) + x vector (2048 f32) + ntot (16 f32) + 16 doubles
#define SMEM_BYTES ((ROWS * MM + MM + 16) * 4 + 16 * 8)

// -------- persistent device state (monotonic; re-derived every launch) ------
__device__ float        g_x[MM];            // rho[:,0] (phase-A input vector)
__device__ float        g_p[MM];            // infect_prob (phase-B input vector)
__device__ float        g_part[NBLK * MM];  // per-block column partials (ntot)
__device__ double       g_bsum[NBLK];       // per-block |traj| sums (agreement)
__device__ unsigned int g_bar_in = 0;       // monotonic arrival counter (ONLY word)

// Grid barrier v8 — the arrival counter IS the release (single hop).
// Every prior design (R3/R9/R12/R13/R14) had a 2-hop chain: last-arrival RMW
// -> separate release store -> visibility -> poll. All converged to ~2.0us
// regardless of arrival topology, wait primitive, or fence drain set — the
// shared cost was the second hop. Here pollers watch g_bar_in itself:
// the 128th atomicAdd is simultaneously arrival and release.
//   arrive:  __threadfence ; relaxed atomicAdd(&g_bar_in)
//   wait:    sleepless ld.relaxed.gpu poll of g_bar_in until >= (gen+1)*128
//            (dependent-load loop: self-throttled to ~1 poll per L2 RTT;
//             relaxed GPU-scope polling measured non-toxic in R12/R13)
//   acquire: __threadfence after detection (last arriver: its RMW read the
//            full count => reads-from chain covers all 127 peers; fence
//            after RMW gives it acquire as well)
// Monotonic: g_bar_in == gen*128 at every launch boundary => graph-replay
// safe; gen re-derived from the counter at kernel start.
__device__ __forceinline__ void gridsync(unsigned int &gen) {
    __syncthreads();
    if (threadIdx.x == 0) {
        const unsigned int tgt = (gen + 1u) * (unsigned)NBLK;
        __threadfence();                                   // publish writes (release)
        unsigned int a = atomicAdd(&g_bar_in, 1u);
        if (a != tgt - 1u) {                               // not the last arriver
            unsigned int f;
            do {   // dependent relaxed load: one L2 round trip per iteration
                asm volatile("ld.relaxed.gpu.u32 %0, [%1];"
                             : "=r"(f) : "l"(&g_bar_in) : "memory");
            } while ((int)(f - tgt) < 0);
        }
        __threadfence();                                   // acquire side
        gen++;
    }
    __syncthreads();
}

__global__ void __launch_bounds__(NTHREADS, 1)
metasim_kernel(const float* __restrict__ Rg,
               const float* __restrict__ Tg,
               const float* __restrict__ rho0,
               float* __restrict__ out,
               int out_size)
{
    extern __shared__ float smem[];
    float*  Rs     = smem;                 // [ROWS][MM]
    float*  xs     = Rs + ROWS * MM;       // [MM]
    float*  ntot_s = xs + MM;              // [ROWS]
    double* dsum   = (double*)(ntot_s + 16); // [16], 8B-aligned

    const int tid     = threadIdx.x;
    const int blk     = blockIdx.x;
    const int w       = tid >> 5;
    const int lane    = tid & 31;
    const int rowbase = blk * ROWS;

    unsigned int gen = 0;
    if (tid == 0) {
        unsigned int c0;
        asm volatile("ld.relaxed.gpu.u32 %0, [%1];"
                     : "=r"(c0) : "l"(&g_bar_in) : "memory");
        gen = c0 / (unsigned)NBLK;         // exact multiple at launch boundary
    }

    // ---- load this block's 16 rows of R into SMEM (once) ----
    {
        const float4* Rg4 = (const float4*)Rg + (size_t)rowbase * (MM / 4);
        float4* Rs4 = (float4*)Rs;
        #pragma unroll 4
        for (int k = tid; k < ROWS * MM / 4; k += NTHREADS) Rs4[k] = Rg4[k];
    }

    // ---- T (4x4) into registers ----
    float Tr[16];
    #pragma unroll
    for (int i = 0; i < 16; i++) Tr[i] = Tg[i];

    // ---- per-lane rho state: lane 0 -> row 2w, lane 1 -> row 2w+1 ----
    const int myrow = rowbase + 2 * w + lane;   // meaningful for lane < 2
    float r0 = 0.f, r1 = 0.f, r2 = 0.f, r3 = 0.f, kk = 0.f;
    if (lane < 2) {
        r0 = rho0[myrow * 4 + 0];
        r1 = rho0[myrow * 4 + 1];
        r2 = rho0[myrow * 4 + 2];
        r3 = rho0[myrow * 4 + 3];
        __stcg(&g_x[myrow], r0);                // initial x = rho0[:,0]
    }
    __syncthreads();                            // Rs ready for column sums

    // ---- deterministic ntot: per-block column partials (no float atomics) ----
    for (int c = tid; c < MM; c += NTHREADS) {
        float s = 0.f;
        #pragma unroll
        for (int r = 0; r < ROWS; r++) s += Rs[r * MM + c];
        __stcg(&g_part[blk * MM + c], s);
    }

    gridsync(gen);                              // partials + g_x visible

    // ntot for own 16 columns (== own row indices), fixed summation order
    if (tid < ROWS) {
        const int c = rowbase + tid;
        float s = 0.f;
        for (int bb = 0; bb < NBLK; bb++) s += __ldcg(&g_part[bb * MM + c]);
        ntot_s[tid] = s;
    }
    __syncthreads();
    if (lane < 2) kk = -BETA_F / ntot_s[2 * w + lane];

    const float4* Rw0 = (const float4*)(Rs + (2 * w) * MM);
    const float4* Rw1 = (const float4*)(Rs + (2 * w + 1) * MM);
    float4* xs4 = (float4*)xs;

    double dAcc = 0.0;

    for (int t = 0; t < NSTEPS; t++) {
        // ================= Phase A: frac = R @ x, p = 1 - exp(-beta*frac/ntot)
        {
            const float4* gx4 = (const float4*)g_x;
            #pragma unroll
            for (int k = tid; k < MM / 4; k += NTHREADS) xs4[k] = __ldcg(gx4 + k);
        }
        __syncthreads();

        float a0 = 0.f, a1 = 0.f;
        #pragma unroll
        for (int j = 0; j < 16; j++) {
            const int c = j * 32 + lane;
            const float4 xv = xs4[c];
            const float4 u = Rw0[c];
            const float4 v = Rw1[c];
            a0 += u.x * xv.x + u.y * xv.y + u.z * xv.z + u.w * xv.w;
            a1 += v.x * xv.x + v.y * xv.y + v.z * xv.z + v.w * xv.w;
        }
        #pragma unroll
        for (int o = 16; o; o >>= 1) {
            a0 += __shfl_xor_sync(0xffffffffu, a0, o);
            a1 += __shfl_xor_sync(0xffffffffu, a1, o);
        }
        if (lane < 2) {
            const float fr = (lane == 0) ? a0 : a1;
            __stcg(&g_p[myrow], 1.0f - expf(kk * fr));
        }
        gridsync(gen);

        // ================= Phase B: nw = R @ p, compartment update, traj out
        {
            const float4* gp4 = (const float4*)g_p;
            #pragma unroll
            for (int k = tid; k < MM / 4; k += NTHREADS) xs4[k] = __ldcg(gp4 + k);
        }
        __syncthreads();

        float b0 = 0.f, b1 = 0.f;
        #pragma unroll
        for (int j = 0; j < 16; j++) {
            const int c = j * 32 + lane;
            const float4 xv = xs4[c];
            const float4 u = Rw0[c];
            const float4 v = Rw1[c];
            b0 += u.x * xv.x + u.y * xv.y + u.z * xv.z + u.w * xv.w;
            b1 += v.x * xv.x + v.y * xv.y + v.z * xv.z + v.w * xv.w;
        }
        #pragma unroll
        for (int o = 16; o; o >>= 1) {
            b0 += __shfl_xor_sync(0xffffffffu, b0, o);
            b1 += __shfl_xor_sync(0xffffffffu, b1, o);
        }
        if (lane < 2) {
            const float acc = (lane == 0) ? b0 : b1;
            const float s   = r0 + r1 + r2 + r3;
            const float nw  = (1.0f - s) * acc;
            float n0 = r0 * Tr[0] + r1 * Tr[4] + r2 * Tr[8]  + r3 * Tr[12] + nw;
            float n1 = r0 * Tr[1] + r1 * Tr[5] + r2 * Tr[9]  + r3 * Tr[13];
            float n2 = r0 * Tr[2] + r1 * Tr[6] + r2 * Tr[10] + r3 * Tr[14];
            float n3 = r0 * Tr[3] + r1 * Tr[7] + r2 * Tr[11] + r3 * Tr[15];
            n0 = fminf(fmaxf(n0, 0.0f), 1e10f);
            n1 = fminf(fmaxf(n1, 0.0f), 1e10f);
            n2 = fminf(fmaxf(n2, 0.0f), 1e10f);
            n3 = fminf(fmaxf(n3, 0.0f), 1e10f);
            r0 = n0; r1 = n1; r2 = n2; r3 = n3;
            __stcg(&g_x[myrow], n0);                      // next step's x

            const float S = 1.0f - (n0 + n1 + n2 + n3);   // AddSusceptibleLayer
            float* o = out + ((size_t)t * MM + myrow) * (NC + 1);
            o[0] = S; o[1] = n0; o[2] = n1; o[3] = n2; o[4] = n3;
            dAcc += (double)(fabsf(S) + fabsf(n0) + fabsf(n1) + fabsf(n2) + fabsf(n3));
        }
        gridsync(gen);
    }

    // ---- agreement = mean(|traj|), fully deterministic reduction ----
    if (lane < 2) dsum[2 * w + lane] = dAcc;
    __syncthreads();
    if (tid == 0) {
        double s = 0.0;
        for (int i = 0; i < 16; i++) s += dsum[i];
        __stcg(&g_bsum[blk], s);
    }
    gridsync(gen);
    if (blk == 0 && tid == 0 && out_size > TRAJ_ELEMS) {
        double s = 0.0;
        for (int i = 0; i < NBLK; i++) s += __ldcg(&g_bsum[i]);
        out[TRAJ_ELEMS] = (float)(s / (double)TRAJ_ELEMS);
    }
}

extern "C" void kernel_launch(void* const* d_in, const int* in_sizes, int n_in,
                              void* d_out, int out_size)
{
    // Identify inputs by element count: R: 2048*2048, T: 4*4, rho0: 2048*4
    const float* R    = nullptr;
    const float* Tm   = nullptr;
    const float* rho0 = nullptr;
    for (int i = 0; i < n_in; i++) {
        if      (in_sizes[i] == MM * MM) R    = (const float*)d_in[i];
        else if (in_sizes[i] == NC * NC) Tm   = (const float*)d_in[i];
        else if (in_sizes[i] == MM * NC) rho0 = (const float*)d_in[i];
    }
    if (!R    && n_in > 0) R    = (const float*)d_in[0];
    if (!Tm   && n_in > 1) Tm   = (const float*)d_in[1];
    if (!rho0 && n_in > 2) rho0 = (const float*)d_in[2];

    cudaFuncSetAttribute(metasim_kernel,
                         cudaFuncAttributeMaxDynamicSharedMemorySize,
                         SMEM_BYTES);

    metasim_kernel<<<NBLK, NTHREADS, SMEM_BYTES>>>(R, Tm, rho0,
                                                   (float*)d_out, out_size);
}

// round 16
// speedup vs baseline: 1.1775x; 1.0892x over previous
#include <cuda_runtime.h>
#include <cuda_fp16.h>
#include <math.h>

// Problem constants
#define MM       2048           // patches
#define NC       4              // compartments
#define NSTEPS   128
#define BETA_F   0.25f
#define TRAJ_ELEMS (NSTEPS * MM * (NC + 1))   // 1310720

// 128 persistent blocks, 16 rows of R each, 256 threads (8 warps).
// Warp w: rows 4*(w>>1)..+3 over column half (w&1)  [split-K].
#define NBLK     128
#define ROWS     16
#define NTHREADS 256

// SMEM: R fp16 tile (64KB) + xs_e/xs_o (4KB each) + part[32] + ntot[16] + dsum
#define SMEM_BYTES (ROWS * MM * 2 + 2 * (MM / 2) * 4 + 32 * 4 + 16 * 4 + 16 * 8)

// -------- persistent device state (monotonic; re-derived every launch) ------
__device__ float        g_x[MM];            // rho[:,0] (phase-A input vector)
__device__ float        g_p[MM];            // infect_prob (phase-B input vector)
__device__ float        g_part[NBLK * MM];  // per-block column partials (ntot)
__device__ double       g_bsum[NBLK];       // per-block |traj| sums (agreement)
__device__ unsigned int g_bar_in = 0;       // monotonic arrival counter (ONLY word)

// R15 barrier, unchanged (best measured; ~7 designs all converge here):
// single word, arrival == release, sleepless GPU-scope relaxed poll,
// fence-fence ordering, monotonic => CUDA-graph-replay safe.
__device__ __forceinline__ void gridsync(unsigned int &gen) {
    __syncthreads();
    if (threadIdx.x == 0) {
        const unsigned int tgt = (gen + 1u) * (unsigned)NBLK;
        __threadfence();                                   // publish writes (release)
        unsigned int a = atomicAdd(&g_bar_in, 1u);
        if (a != tgt - 1u) {                               // not the last arriver
            unsigned int f;
            do {   // dependent relaxed load: one L2 round trip per iteration
                asm volatile("ld.relaxed.gpu.u32 %0, [%1];"
                             : "=r"(f) : "l"(&g_bar_in) : "memory");
            } while ((int)(f - tgt) < 0);
        }
        __threadfence();                                   // acquire side
        gen++;
    }
    __syncthreads();
}

__global__ void __launch_bounds__(NTHREADS, 1)
metasim_kernel(const float* __restrict__ Rg,
               const float* __restrict__ Tg,
               const float* __restrict__ rho0,
               float* __restrict__ out,
               int out_size)
{
    extern __shared__ char smem_raw[];
    __half* Rs_h   = (__half*)smem_raw;                    // [ROWS][MM] fp16
    float4* xs_e   = (float4*)(smem_raw + ROWS * MM * 2);  // even float4s of x
    float4* xs_o   = xs_e + MM / 8;                        // odd  float4s of x
    float*  part   = (float*)(xs_o + MM / 8);              // [16 rows][2 halves]
    float*  ntot_s = part + 32;                            // [16]
    double* dsum   = (double*)(ntot_s + 16);               // [16], 8B aligned

    const int tid     = threadIdx.x;
    const int blk     = blockIdx.x;
    const int w       = tid >> 5;
    const int lane    = tid & 31;
    const int rowbase = blk * ROWS;
    const int row0    = 4 * (w >> 1);       // warp's 4-row group
    const int colhalf = w & 1;              // 0: cols 0..1023, 1: 1024..2047

    unsigned int gen = 0;
    if (tid == 0) {
        unsigned int c0;
        asm volatile("ld.relaxed.gpu.u32 %0, [%1];"
                     : "=r"(c0) : "l"(&g_bar_in) : "memory");
        gen = c0 / (unsigned)NBLK;          // exact multiple at launch boundary
    }

    // ---- convert this block's 16 fp32 R rows into fp16 SMEM (once) ----
    {
        const float4* Rg4 = (const float4*)Rg + (size_t)rowbase * (MM / 4);
        half2* Rs2 = (half2*)Rs_h;
        #pragma unroll 4
        for (int k = tid; k < ROWS * MM / 4; k += NTHREADS) {
            const float4 v = Rg4[k];
            Rs2[2 * k]     = __floats2half2_rn(v.x, v.y);
            Rs2[2 * k + 1] = __floats2half2_rn(v.z, v.w);
        }
    }

    // ---- per-row state lives in tid<16 (fp32 everywhere except R tile) ----
    const int myrow = rowbase + tid;        // valid for tid < ROWS
    float r0 = 0.f, r1 = 0.f, r2 = 0.f, r3 = 0.f, kk = 0.f;
    float Tr[16];
    if (tid < ROWS) {
        #pragma unroll
        for (int i = 0; i < 16; i++) Tr[i] = Tg[i];
        r0 = rho0[myrow * 4 + 0];
        r1 = rho0[myrow * 4 + 1];
        r2 = rho0[myrow * 4 + 2];
        r3 = rho0[myrow * 4 + 3];
        __stcg(&g_x[myrow], r0);            // initial x = rho0[:,0]
    }

    // ---- deterministic ntot from EXACT fp32 global R (column partials) ----
    for (int c = tid; c < MM; c += NTHREADS) {
        float s = 0.f;
        #pragma unroll
        for (int r = 0; r < ROWS; r++) s += Rg[(size_t)(rowbase + r) * MM + c];
        __stcg(&g_part[blk * MM + c], s);
    }

    gridsync(gen);                          // partials + g_x visible grid-wide

    if (tid < ROWS) {                       // ntot for own rows, fixed sum order
        float s = 0.f;
        #pragma unroll 8
        for (int bb = 0; bb < NBLK; bb++) s += __ldcg(&g_part[bb * MM + myrow]);
        ntot_s[tid] = s;
        kk = -BETA_F / s;
    }

    // warp's 4 fp16 R-row pointers (uint4 = 8 halves); c = colhalf*128+j*32+lane
    const uint4* R0 = (const uint4*)(Rs_h + (size_t)(row0 + 0) * MM);
    const uint4* R1 = (const uint4*)(Rs_h + (size_t)(row0 + 1) * MM);
    const uint4* R2 = (const uint4*)(Rs_h + (size_t)(row0 + 2) * MM);
    const uint4* R3 = (const uint4*)(Rs_h + (size_t)(row0 + 3) * MM);

    double dAcc = 0.0;

    // dot helper macro: accumulate 8 cols (one uint4 of halves) into acc
    #define DOT8(acc, q, xvA, xvB) do {                                      \
        const half2* _h = (const half2*)&(q);                                \
        const float2 _f0 = __half22float2(_h[0]);                            \
        const float2 _f1 = __half22float2(_h[1]);                            \
        const float2 _f2 = __half22float2(_h[2]);                            \
        const float2 _f3 = __half22float2(_h[3]);                            \
        (acc) += _f0.x*(xvA).x + _f0.y*(xvA).y + _f1.x*(xvA).z + _f1.y*(xvA).w \
               + _f2.x*(xvB).x + _f2.y*(xvB).y + _f3.x*(xvB).z + _f3.y*(xvB).w; \
    } while (0)

    for (int t = 0; t < NSTEPS; t++) {
        // ===== Phase A: frac = R @ x ; p = 1 - exp(-beta*frac/ntot) =====
        {   // stage x split even/odd so all dot LDS are conflict-free
            const float4* gx4 = (const float4*)g_x;
            xs_e[tid] = __ldcg(gx4 + 2 * tid);
            xs_o[tid] = __ldcg(gx4 + 2 * tid + 1);
        }
        __syncthreads();
        {
            float a0 = 0.f, a1 = 0.f, a2 = 0.f, a3 = 0.f;
            #pragma unroll
            for (int j = 0; j < 4; j++) {
                const int c = colhalf * 128 + j * 32 + lane;
                const float4 xvA = xs_e[c];
                const float4 xvB = xs_o[c];
                const uint4 q0 = R0[c]; DOT8(a0, q0, xvA, xvB);
                const uint4 q1 = R1[c]; DOT8(a1, q1, xvA, xvB);
                const uint4 q2 = R2[c]; DOT8(a2, q2, xvA, xvB);
                const uint4 q3 = R3[c]; DOT8(a3, q3, xvA, xvB);
            }
            #pragma unroll
            for (int o = 16; o; o >>= 1) {
                a0 += __shfl_xor_sync(0xffffffffu, a0, o);
                a1 += __shfl_xor_sync(0xffffffffu, a1, o);
                a2 += __shfl_xor_sync(0xffffffffu, a2, o);
                a3 += __shfl_xor_sync(0xffffffffu, a3, o);
            }
            if (lane == 0) {
                part[(row0 + 0) * 2 + colhalf] = a0;
                part[(row0 + 1) * 2 + colhalf] = a1;
                part[(row0 + 2) * 2 + colhalf] = a2;
                part[(row0 + 3) * 2 + colhalf] = a3;
            }
        }
        __syncthreads();
        if (tid < ROWS) {
            const float fr = part[2 * tid] + part[2 * tid + 1];
            __stcg(&g_p[myrow], 1.0f - expf(kk * fr));
        }
        gridsync(gen);

        // ===== Phase B: nw = R @ p ; compartment update ; traj out =====
        {
            const float4* gp4 = (const float4*)g_p;
            xs_e[tid] = __ldcg(gp4 + 2 * tid);
            xs_o[tid] = __ldcg(gp4 + 2 * tid + 1);
        }
        __syncthreads();
        {
            float a0 = 0.f, a1 = 0.f, a2 = 0.f, a3 = 0.f;
            #pragma unroll
            for (int j = 0; j < 4; j++) {
                const int c = colhalf * 128 + j * 32 + lane;
                const float4 xvA = xs_e[c];
                const float4 xvB = xs_o[c];
                const uint4 q0 = R0[c]; DOT8(a0, q0, xvA, xvB);
                const uint4 q1 = R1[c]; DOT8(a1, q1, xvA, xvB);
                const uint4 q2 = R2[c]; DOT8(a2, q2, xvA, xvB);
                const uint4 q3 = R3[c]; DOT8(a3, q3, xvA, xvB);
            }
            #pragma unroll
            for (int o = 16; o; o >>= 1) {
                a0 += __shfl_xor_sync(0xffffffffu, a0, o);
                a1 += __shfl_xor_sync(0xffffffffu, a1, o);
                a2 += __shfl_xor_sync(0xffffffffu, a2, o);
                a3 += __shfl_xor_sync(0xffffffffu, a3, o);
            }
            if (lane == 0) {
                part[(row0 + 0) * 2 + colhalf] = a0;
                part[(row0 + 1) * 2 + colhalf] = a1;
                part[(row0 + 2) * 2 + colhalf] = a2;
                part[(row0 + 3) * 2 + colhalf] = a3;
            }
        }
        __syncthreads();
        if (tid < ROWS) {
            const float acc = part[2 * tid] + part[2 * tid + 1];
            const float s   = r0 + r1 + r2 + r3;
            const float nw  = (1.0f - s) * acc;
            float n0 = r0 * Tr[0] + r1 * Tr[4] + r2 * Tr[8]  + r3 * Tr[12] + nw;
            float n1 = r0 * Tr[1] + r1 * Tr[5] + r2 * Tr[9]  + r3 * Tr[13];
            float n2 = r0 * Tr[2] + r1 * Tr[6] + r2 * Tr[10] + r3 * Tr[14];
            float n3 = r0 * Tr[3] + r1 * Tr[7] + r2 * Tr[11] + r3 * Tr[15];
            n0 = fminf(fmaxf(n0, 0.0f), 1e10f);
            n1 = fminf(fmaxf(n1, 0.0f), 1e10f);
            n2 = fminf(fmaxf(n2, 0.0f), 1e10f);
            n3 = fminf(fmaxf(n3, 0.0f), 1e10f);
            r0 = n0; r1 = n1; r2 = n2; r3 = n3;
            __stcg(&g_x[myrow], n0);                      // next step's x

            const float S = 1.0f - (n0 + n1 + n2 + n3);   // AddSusceptibleLayer
            float* o = out + ((size_t)t * MM + myrow) * (NC + 1);
            o[0] = S; o[1] = n0; o[2] = n1; o[3] = n2; o[4] = n3;
            dAcc += (double)(fabsf(S) + fabsf(n0) + fabsf(n1) + fabsf(n2) + fabsf(n3));
        }
        gridsync(gen);
    }
    #undef DOT8

    // ---- agreement = mean(|traj|), fully deterministic reduction ----
    if (tid < ROWS) dsum[tid] = dAcc;
    __syncthreads();
    if (tid == 0) {
        double s = 0.0;
        for (int i = 0; i < ROWS; i++) s += dsum[i];
        __stcg(&g_bsum[blk], s);
    }
    gridsync(gen);
    if (blk == 0 && tid == 0 && out_size > TRAJ_ELEMS) {
        double s = 0.0;
        for (int i = 0; i < NBLK; i++) s += __ldcg(&g_bsum[i]);
        out[TRAJ_ELEMS] = (float)(s / (double)TRAJ_ELEMS);
    }
}

extern "C" void kernel_launch(void* const* d_in, const int* in_sizes, int n_in,
                              void* d_out, int out_size)
{
    // Identify inputs by element count: R: 2048*2048, T: 4*4, rho0: 2048*4
    const float* R    = nullptr;
    const float* Tm   = nullptr;
    const float* rho0 = nullptr;
    for (int i = 0; i < n_in; i++) {
        if      (in_sizes[i] == MM * MM) R    = (const float*)d_in[i];
        else if (in_sizes[i] == NC * NC) Tm   = (const float*)d_in[i];
        else if (in_sizes[i] == MM * NC) rho0 = (const float*)d_in[i];
    }
    if (!R    && n_in > 0) R    = (const float*)d_in[0];
    if (!Tm   && n_in > 1) Tm   = (const float*)d_in[1];
    if (!rho0 && n_in > 2) rho0 = (const float*)d_in[2];

    cudaFuncSetAttribute(metasim_kernel,
                         cudaFuncAttributeMaxDynamicSharedMemorySize,
                         SMEM_BYTES);

    metasim_kernel<<<NBLK, NTHREADS, SMEM_BYTES>>>(R, Tm, rho0,
                                                   (float*)d_out, out_size);
}